// round 1
// baseline (speedup 1.0000x reference)
#include <cuda_runtime.h>
#include <cuda_bf16.h>

#define BATCH 64
#define NTOK  4096
#define CH    512
#define NUM_KEEP 2458            // ceil(4096 * 0.6)
#define TAIL (NTOK - NUM_KEEP)   // 1638
#define C4   (CH / 4)            // 128 float4 per token row

// scratch (device globals: no allocation allowed)
__device__ int   g_sorted_idx[BATCH * NTOK];
__device__ float g_tailw[BATCH * TAIL];

// ---------------------------------------------------------------------------
// Kernel 1: per-batch-row bitonic sort of (score, idx), mask write, softmax
// weights for the tail. One CTA (1024 threads) per batch row.
// ---------------------------------------------------------------------------
__global__ __launch_bounds__(1024)
void ts_sort_kernel(const float* __restrict__ ax,
                    const float* __restrict__ ay,
                    float* __restrict__ mask_out)
{
    __shared__ unsigned long long key[NTOK];       // 32 KB
    __shared__ float tailw_sh[TAIL];               // 6.4 KB
    __shared__ float red[32];

    const int b   = blockIdx.x;
    const int tid = threadIdx.x;

    // build orderable 64-bit keys: (flipped score << 32) | ~idx
    for (int i = tid; i < NTOK; i += 1024) {
        float s = ax[b * NTOK + i] + ay[b * NTOK + i];
        unsigned u = __float_as_uint(s);
        u = (u & 0x80000000u) ? ~u : (u | 0x80000000u);   // monotone map
        key[i] = ((unsigned long long)u << 32) | (unsigned)(~i);
    }
    __syncthreads();

    // bitonic sort, DESCENDING
    for (int k = 2; k <= NTOK; k <<= 1) {
        for (int j = k >> 1; j > 0; j >>= 1) {
            #pragma unroll
            for (int t = 0; t < NTOK / 1024; ++t) {
                int i = tid + t * 1024;
                int ixj = i ^ j;
                if (ixj > i) {
                    unsigned long long a = key[i];
                    unsigned long long c = key[ixj];
                    bool desc = ((i & k) == 0);
                    bool swp  = desc ? (a < c) : (a > c);
                    if (swp) { key[i] = c; key[ixj] = a; }
                }
            }
            __syncthreads();
        }
    }

    // softmax max = largest tail score (rank NUM_KEEP)
    unsigned um = (unsigned)(key[NUM_KEEP] >> 32);
    float m = (um & 0x80000000u) ? __uint_as_float(um & 0x7FFFFFFFu)
                                 : __uint_as_float(~um);

    // decode: sorted indices, mask, un-normalized tail exp
    float local_sum = 0.f;
    for (int r = tid; r < NTOK; r += 1024) {
        unsigned long long kk = key[r];
        int idx = (int)(~(unsigned)kk);              // recover original index
        g_sorted_idx[b * NTOK + r] = idx;
        mask_out[b * NTOK + idx] = (r < NUM_KEEP) ? 1.0f : 0.0f;
        if (r >= NUM_KEEP) {
            unsigned u = (unsigned)(kk >> 32);
            float s = (u & 0x80000000u) ? __uint_as_float(u & 0x7FFFFFFFu)
                                        : __uint_as_float(~u);
            float e = expf(s - m);
            tailw_sh[r - NUM_KEEP] = e;
            local_sum += e;
        }
    }

    // block-reduce local_sum
    for (int off = 16; off > 0; off >>= 1)
        local_sum += __shfl_down_sync(0xFFFFFFFFu, local_sum, off);
    if ((tid & 31) == 0) red[tid >> 5] = local_sum;
    __syncthreads();
    if (tid < 32) {
        float v = red[tid];
        for (int off = 16; off > 0; off >>= 1)
            v += __shfl_down_sync(0xFFFFFFFFu, v, off);
        if (tid == 0) red[0] = v;
    }
    __syncthreads();
    float inv_sum = 1.0f / red[0];

    // normalized weights -> global scratch
    for (int r = tid; r < TAIL; r += 1024)
        g_tailw[b * TAIL + r] = tailw_sh[r] * inv_sum;
}

// ---------------------------------------------------------------------------
// Kernel 2: gather select_tokens. One CTA (128 threads) per (b, rank) row.
// ---------------------------------------------------------------------------
__global__ __launch_bounds__(128)
void ts_gather_kernel(const float* __restrict__ tokens,
                      float* __restrict__ sel)
{
    const long long t = blockIdx.x;
    const int b = (int)(t / NUM_KEEP);
    const int r = (int)(t % NUM_KEEP);
    const int idx = g_sorted_idx[b * NTOK + r];

    const float4* src = (const float4*)(tokens + ((long long)b * NTOK + idx) * CH);
    float4*       dst = (float4*)(sel + ((long long)b * NUM_KEEP + r) * CH);
    dst[threadIdx.x] = src[threadIdx.x];
}

// ---------------------------------------------------------------------------
// Kernel 3: extra_token = sum_r w_r * tokens[b, nonkeep_r, :].
// One CTA per batch; 512 threads = 4 sub-groups of 128 (float4 lanes) that
// stride over the tail ranks for memory-level parallelism, then reduce.
// ---------------------------------------------------------------------------
__global__ __launch_bounds__(512)
void ts_extra_kernel(const float* __restrict__ tokens,
                     float* __restrict__ extra)
{
    __shared__ float4 part[3][C4];   // groups 1..3 spill here

    const int b    = blockIdx.x;
    const int tid  = threadIdx.x;
    const int g    = tid >> 7;       // sub-group 0..3
    const int lane = tid & 127;      // float4 lane within row

    float4 acc = make_float4(0.f, 0.f, 0.f, 0.f);
    for (int r = g; r < TAIL; r += 4) {
        int idx = g_sorted_idx[b * NTOK + NUM_KEEP + r];
        float w = g_tailw[b * TAIL + r];
        float4 v = ((const float4*)(tokens + ((long long)b * NTOK + idx) * CH))[lane];
        acc.x += w * v.x;
        acc.y += w * v.y;
        acc.z += w * v.z;
        acc.w += w * v.w;
    }

    if (g > 0) part[g - 1][lane] = acc;
    __syncthreads();
    if (g == 0) {
        #pragma unroll
        for (int i = 0; i < 3; ++i) {
            float4 p = part[i][lane];
            acc.x += p.x; acc.y += p.y; acc.z += p.z; acc.w += p.w;
        }
        ((float4*)(extra + (long long)b * CH))[lane] = acc;
    }
}

// ---------------------------------------------------------------------------
// launch: inputs are (tokens, attention_x, attention_y); output is the
// concatenation (select_tokens, extra_token, score_mask) in float32.
// ---------------------------------------------------------------------------
extern "C" void kernel_launch(void* const* d_in, const int* in_sizes, int n_in,
                              void* d_out, int out_size)
{
    const float* tokens = (const float*)d_in[0];
    const float* ax     = (const float*)d_in[1];
    const float* ay     = (const float*)d_in[2];

    float* out = (float*)d_out;
    float* sel   = out;                                              // B*NUM_KEEP*C
    float* extra = out + (long long)BATCH * NUM_KEEP * CH;           // B*C
    float* mask  = extra + (long long)BATCH * CH;                    // B*N

    ts_sort_kernel<<<BATCH, 1024>>>(ax, ay, mask);
    ts_gather_kernel<<<BATCH * NUM_KEEP, 128>>>(tokens, sel);
    ts_extra_kernel<<<BATCH, 512>>>(tokens, extra);
}

// round 2
// speedup vs baseline: 1.8737x; 1.8737x over previous
#include <cuda_runtime.h>
#include <cuda_bf16.h>

#define BATCH 64
#define NTOK  4096
#define CH    512
#define NUM_KEEP 2458            // ceil(4096 * 0.6)
#define TAIL (NTOK - NUM_KEEP)   // 1638
#define C4   (CH / 4)            // 128 float4 per token row
#define NGROUP 32                // tail groups per batch (extra kernel)
#define TOTAL_V (BATCH * NUM_KEEP * C4)   // 20,135,936 float4s in sel
#define GATHER_CTAS 9832         // TOTAL_V / (512 threads * 4 per thread), exact

// scratch (device globals: no allocation allowed)
__device__ int    g_sorted_idx[BATCH * NTOK];
__device__ float  g_tailw[BATCH * TAIL];     // UN-normalized exp weights
__device__ float  g_invsum[BATCH];
__device__ float4 g_part[BATCH * NGROUP * C4];

// ---------------------------------------------------------------------------
// helpers for hybrid bitonic sort (descending)
// ---------------------------------------------------------------------------
__device__ __forceinline__ float decode_score(unsigned long long kk) {
    unsigned u = (unsigned)(kk >> 32);
    return (u & 0x80000000u) ? __uint_as_float(u & 0x7FFFFFFFu)
                             : __uint_as_float(~u);
}

// compare-swap two registers so that r[a] (lower rank) gets the max if desc
__device__ __forceinline__ void cmpswap(unsigned long long& a,
                                        unsigned long long& c, bool desc) {
    bool sw = desc ? (a < c) : (a > c);
    if (sw) { unsigned long long t = a; a = c; c = t; }
}

// shuffle-exchange stage for 4<=j<=64 (element e owned by lane (e>>2)&31)
__device__ __forceinline__ void shfl_stage(unsigned long long r[4],
                                           int base, int k, int j) {
    int L = j >> 2;
    bool lower = ((base & j) == 0);
    bool desc  = ((base & k) == 0);
    bool keepmax = (lower == desc);
    #pragma unroll
    for (int m = 0; m < 4; ++m) {
        unsigned long long o = __shfl_xor_sync(0xFFFFFFFFu, r[m], L);
        r[m] = keepmax ? (r[m] > o ? r[m] : o) : (r[m] < o ? r[m] : o);
    }
}

// warp-local finishing pass: j = min(k/2,64) .. 1 for bitonic step size k
__device__ __forceinline__ void warp_pass(unsigned long long r[4],
                                          int base, int k, int jmax) {
    for (int j = jmax; j >= 4; j >>= 1) shfl_stage(r, base, k, j);
    bool desc = ((base & k) == 0);
    // j = 2 : pairs (0,2) (1,3)
    cmpswap(r[0], r[2], desc);
    cmpswap(r[1], r[3], desc);
    // j = 1 : pairs (0,1) (2,3)
    cmpswap(r[0], r[1], desc);
    cmpswap(r[2], r[3], desc);
}

// ---------------------------------------------------------------------------
// Kernel 1: per-batch hybrid bitonic sort + mask + softmax exp weights.
// 1024 threads, 4 elements/thread in registers; smem only for j>=128 stages.
// ---------------------------------------------------------------------------
__global__ __launch_bounds__(1024)
void ts_sort_kernel(const float* __restrict__ ax,
                    const float* __restrict__ ay,
                    float* __restrict__ mask_out)
{
    __shared__ unsigned long long key[NTOK];   // 32 KB
    __shared__ float red[33];

    const int b    = blockIdx.x;
    const int tid  = threadIdx.x;
    const int base = ((tid >> 5) << 7) | ((tid & 31) << 2);   // first element idx

    // build 4 keys in registers (vectorized float4 reads, contiguous)
    unsigned long long r[4];
    {
        float4 x = *(const float4*)(ax + b * NTOK + base);
        float4 y = *(const float4*)(ay + b * NTOK + base);
        float s[4] = { x.x + y.x, x.y + y.y, x.z + y.z, x.w + y.w };
        #pragma unroll
        for (int m = 0; m < 4; ++m) {
            unsigned u = __float_as_uint(s[m]);
            u = (u & 0x80000000u) ? ~u : (u | 0x80000000u);
            r[m] = ((unsigned long long)u << 32) | (unsigned)(~(base + m));
        }
    }

    // ---- Phase A: k = 2..128 entirely in registers / shuffles ----
    cmpswap(r[0], r[1], true);    // k=2 pair(0,1) desc
    cmpswap(r[2], r[3], false);   // k=2 pair(2,3) asc
    for (int k = 4; k <= 128; k <<= 1)
        warp_pass(r, base, k, (k >> 1) > 64 ? 64 : (k >> 1));

    // ---- Phase B: k = 256..4096 : smem stages for j>=128, then warp pass ----
    for (int k = 256; k <= NTOK; k <<= 1) {
        // flush registers to smem
        #pragma unroll
        for (int m = 0; m < 4; ++m) key[base + m] = r[m];
        __syncthreads();
        for (int j = k >> 1; j >= 128; j >>= 1) {
            #pragma unroll
            for (int t = 0; t < 4; ++t) {
                int i = tid + (t << 10);
                int ixj = i ^ j;
                if (ixj > i) {
                    unsigned long long a = key[i];
                    unsigned long long c = key[ixj];
                    bool desc = ((i & k) == 0);
                    bool sw = desc ? (a < c) : (a > c);
                    if (sw) { key[i] = c; key[ixj] = a; }
                }
            }
            __syncthreads();
        }
        #pragma unroll
        for (int m = 0; m < 4; ++m) r[m] = key[base + m];
        warp_pass(r, base, k, 64);
    }
    // registers now hold ranks base..base+3, descending order

    // broadcast softmax max = score at rank NUM_KEEP
    if (base <= NUM_KEEP && NUM_KEEP < base + 4)
        red[32] = decode_score(r[NUM_KEEP - base]);
    __syncthreads();
    const float mx = red[32];

    // decode: sorted idx, mask, unnormalized tail exp
    float local_sum = 0.f;
    int idx4[4];
    #pragma unroll
    for (int m = 0; m < 4; ++m) {
        int rank = base + m;
        int idx = (int)(~(unsigned)r[m]);
        idx4[m] = idx;
        mask_out[b * NTOK + idx] = (rank < NUM_KEEP) ? 1.0f : 0.0f;
        if (rank >= NUM_KEEP) {
            float e = expf(decode_score(r[m]) - mx);
            g_tailw[b * TAIL + (rank - NUM_KEEP)] = e;
            local_sum += e;
        }
    }
    *(int4*)(g_sorted_idx + b * NTOK + base) =
        make_int4(idx4[0], idx4[1], idx4[2], idx4[3]);

    // block-reduce local_sum -> inverse sum
    for (int off = 16; off > 0; off >>= 1)
        local_sum += __shfl_down_sync(0xFFFFFFFFu, local_sum, off);
    if ((tid & 31) == 0) red[tid >> 5] = local_sum;
    __syncthreads();
    if (tid < 32) {
        float v = red[tid];
        for (int off = 16; off > 0; off >>= 1)
            v += __shfl_down_sync(0xFFFFFFFFu, v, off);
        if (tid == 0) g_invsum[b] = 1.0f / v;
    }
}

// ---------------------------------------------------------------------------
// Kernel 2: gather select_tokens with MLP=4.
// Each thread copies 4 float4s from 4 independent token rows.
// grid * block * 4 == TOTAL_V exactly (no guards).
// ---------------------------------------------------------------------------
__global__ __launch_bounds__(512)
void ts_gather_kernel(const float* __restrict__ tokens,
                      float* __restrict__ sel)
{
    const int stride = GATHER_CTAS * 512;
    const int v0 = blockIdx.x * 512 + threadIdx.x;

    long long srcoff[4];
    int vv[4];
    #pragma unroll
    for (int i = 0; i < 4; ++i) {
        int v = v0 + i * stride;
        vv[i] = v;
        int row  = v >> 7;                 // b*NUM_KEEP + r
        int lane = v & 127;
        int b = row / NUM_KEEP;
        int r = row - b * NUM_KEEP;
        int idx = __ldg(&g_sorted_idx[b * NTOK + r]);
        srcoff[i] = (((long long)b * NTOK + idx) << 7) + lane;
    }
    float4 val[4];
    #pragma unroll
    for (int i = 0; i < 4; ++i)
        val[i] = ((const float4*)tokens)[srcoff[i]];
    #pragma unroll
    for (int i = 0; i < 4; ++i)
        ((float4*)sel)[vv[i]] = val[i];
}

// ---------------------------------------------------------------------------
// Kernel 3a: extra_token partial sums. 16 CTAs per batch, 256 threads
// = 2 groups of 128 lanes -> 32 groups per batch striding over tail rows.
// ---------------------------------------------------------------------------
__global__ __launch_bounds__(256)
void ts_extra_partial(const float* __restrict__ tokens)
{
    const int b    = blockIdx.x >> 4;
    const int g    = ((blockIdx.x & 15) << 1) | (threadIdx.x >> 7);  // 0..31
    const int lane = threadIdx.x & 127;

    const int* __restrict__ sidx = g_sorted_idx + b * NTOK + NUM_KEEP;
    const float* __restrict__ w  = g_tailw + b * TAIL;
    const float4* __restrict__ tok4 = (const float4*)tokens
                                      + ((long long)b * NTOK << 7);

    float4 acc = make_float4(0.f, 0.f, 0.f, 0.f);
    int r = g;
    // software-pipelined by 2 for MLP on the dependent idx->row chains
    for (; r + NGROUP < TAIL; r += 2 * NGROUP) {
        int   i0 = sidx[r],           i1 = sidx[r + NGROUP];
        float w0 = w[r],              w1 = w[r + NGROUP];
        float4 v0 = tok4[((long long)i0 << 7) + lane];
        float4 v1 = tok4[((long long)i1 << 7) + lane];
        acc.x += w0 * v0.x + w1 * v1.x;
        acc.y += w0 * v0.y + w1 * v1.y;
        acc.z += w0 * v0.z + w1 * v1.z;
        acc.w += w0 * v0.w + w1 * v1.w;
    }
    if (r < TAIL) {
        int i0 = sidx[r];
        float w0 = w[r];
        float4 v0 = tok4[((long long)i0 << 7) + lane];
        acc.x += w0 * v0.x; acc.y += w0 * v0.y;
        acc.z += w0 * v0.z; acc.w += w0 * v0.w;
    }
    g_part[(b * NGROUP + g) * C4 + lane] = acc;
}

// ---------------------------------------------------------------------------
// Kernel 3b: reduce the 32 partials per batch, apply softmax normalization.
// ---------------------------------------------------------------------------
__global__ __launch_bounds__(128)
void ts_extra_reduce(float* __restrict__ extra)
{
    const int b    = blockIdx.x;
    const int lane = threadIdx.x;
    float4 acc = make_float4(0.f, 0.f, 0.f, 0.f);
    #pragma unroll
    for (int g = 0; g < NGROUP; ++g) {
        float4 p = g_part[(b * NGROUP + g) * C4 + lane];
        acc.x += p.x; acc.y += p.y; acc.z += p.z; acc.w += p.w;
    }
    float s = g_invsum[b];
    acc.x *= s; acc.y *= s; acc.z *= s; acc.w *= s;
    ((float4*)(extra + (long long)b * CH))[lane] = acc;
}

// ---------------------------------------------------------------------------
extern "C" void kernel_launch(void* const* d_in, const int* in_sizes, int n_in,
                              void* d_out, int out_size)
{
    const float* tokens = (const float*)d_in[0];
    const float* ax     = (const float*)d_in[1];
    const float* ay     = (const float*)d_in[2];

    float* out = (float*)d_out;
    float* sel   = out;                                      // B*NUM_KEEP*C
    float* extra = out + (long long)BATCH * NUM_KEEP * CH;   // B*C
    float* mask  = extra + (long long)BATCH * CH;            // B*N

    ts_sort_kernel<<<BATCH, 1024>>>(ax, ay, mask);
    ts_gather_kernel<<<GATHER_CTAS, 512>>>(tokens, sel);
    ts_extra_partial<<<BATCH * 16, 256>>>(tokens);
    ts_extra_reduce<<<BATCH, 128>>>(extra);
}

// round 3
// speedup vs baseline: 2.0690x; 1.1042x over previous
#include <cuda_runtime.h>
#include <cuda_bf16.h>

#define BATCH 64
#define NTOK  4096
#define CH    512
#define NUM_KEEP 2458            // ceil(4096 * 0.6)
#define TAIL (NTOK - NUM_KEEP)   // 1638
#define C4   (CH / 4)            // 128 float4 per token row
#define NGROUP 32                // tail groups per batch
#define TAIL_CTAS (BATCH * 8)    // 512 CTAs, 4 groups of 128 lanes each
#define COPY_CTAS 4916           // TOTAL_V / 4096 float4s per CTA, exact
#define TOTAL_V (BATCH * NUM_KEEP * C4)   // 20,135,936

// scratch (device globals: no allocation allowed)
__device__ int    g_sorted_idx[BATCH * NTOK];
__device__ float  g_tailw[BATCH * TAIL];     // UN-normalized exp weights
__device__ float  g_invsum[BATCH];

// ---------------------------------------------------------------------------
// sort helpers (descending bitonic, 64-bit packed keys)
// ---------------------------------------------------------------------------
__device__ __forceinline__ float decode_score(unsigned long long kk) {
    unsigned u = (unsigned)(kk >> 32);
    return (u & 0x80000000u) ? __uint_as_float(u & 0x7FFFFFFFu)
                             : __uint_as_float(~u);
}

__device__ __forceinline__ void cmpswap(unsigned long long& a,
                                        unsigned long long& c, bool desc) {
    bool sw = desc ? (a < c) : (a > c);
    if (sw) { unsigned long long t = a; a = c; c = t; }
}

__device__ __forceinline__ void shfl_stage(unsigned long long r[4],
                                           int base, int k, int j) {
    int L = j >> 2;
    bool lower = ((base & j) == 0);
    bool desc  = ((base & k) == 0);
    bool keepmax = (lower == desc);
    #pragma unroll
    for (int m = 0; m < 4; ++m) {
        unsigned long long o = __shfl_xor_sync(0xFFFFFFFFu, r[m], L);
        r[m] = keepmax ? (r[m] > o ? r[m] : o) : (r[m] < o ? r[m] : o);
    }
}

__device__ __forceinline__ void warp_pass(unsigned long long r[4],
                                          int base, int k, int jmax) {
    for (int j = jmax; j >= 4; j >>= 1) shfl_stage(r, base, k, j);
    bool desc = ((base & k) == 0);
    cmpswap(r[0], r[2], desc);
    cmpswap(r[1], r[3], desc);
    cmpswap(r[0], r[1], desc);
    cmpswap(r[2], r[3], desc);
}

// ---------------------------------------------------------------------------
// Kernel 1: per-batch hybrid bitonic sort + mask + exp weights + zero extra.
// ---------------------------------------------------------------------------
__global__ __launch_bounds__(1024)
void ts_sort_kernel(const float* __restrict__ ax,
                    const float* __restrict__ ay,
                    float* __restrict__ mask_out,
                    float* __restrict__ extra)
{
    __shared__ unsigned long long key[NTOK];   // 32 KB
    __shared__ float red[33];

    const int b    = blockIdx.x;
    const int tid  = threadIdx.x;
    const int base = ((tid >> 5) << 7) | ((tid & 31) << 2);

    // zero this batch's extra-token slice (output poisoned; tail atomics add)
    if (tid < CH) extra[b * CH + tid] = 0.0f;

    unsigned long long r[4];
    {
        float4 x = *(const float4*)(ax + b * NTOK + base);
        float4 y = *(const float4*)(ay + b * NTOK + base);
        float s[4] = { x.x + y.x, x.y + y.y, x.z + y.z, x.w + y.w };
        #pragma unroll
        for (int m = 0; m < 4; ++m) {
            unsigned u = __float_as_uint(s[m]);
            u = (u & 0x80000000u) ? ~u : (u | 0x80000000u);
            r[m] = ((unsigned long long)u << 32) | (unsigned)(~(base + m));
        }
    }

    // Phase A: k = 2..128 in registers / shuffles
    cmpswap(r[0], r[1], true);
    cmpswap(r[2], r[3], false);
    for (int k = 4; k <= 128; k <<= 1)
        warp_pass(r, base, k, (k >> 1) > 64 ? 64 : (k >> 1));

    // Phase B: k = 256..4096 : smem for j>=128, warp finish
    for (int k = 256; k <= NTOK; k <<= 1) {
        #pragma unroll
        for (int m = 0; m < 4; ++m) key[base + m] = r[m];
        __syncthreads();
        for (int j = k >> 1; j >= 128; j >>= 1) {
            #pragma unroll
            for (int t = 0; t < 4; ++t) {
                int i = tid + (t << 10);
                int ixj = i ^ j;
                if (ixj > i) {
                    unsigned long long a = key[i];
                    unsigned long long c = key[ixj];
                    bool desc = ((i & k) == 0);
                    bool sw = desc ? (a < c) : (a > c);
                    if (sw) { key[i] = c; key[ixj] = a; }
                }
            }
            __syncthreads();
        }
        #pragma unroll
        for (int m = 0; m < 4; ++m) r[m] = key[base + m];
        warp_pass(r, base, k, 64);
    }

    // softmax max = score at rank NUM_KEEP
    if (base <= NUM_KEEP && NUM_KEEP < base + 4)
        red[32] = decode_score(r[NUM_KEEP - base]);
    __syncthreads();
    const float mx = red[32];

    float local_sum = 0.f;
    int idx4[4];
    #pragma unroll
    for (int m = 0; m < 4; ++m) {
        int rank = base + m;
        int idx = (int)(~(unsigned)r[m]);
        idx4[m] = idx;
        mask_out[b * NTOK + idx] = (rank < NUM_KEEP) ? 1.0f : 0.0f;
        if (rank >= NUM_KEEP) {
            float e = expf(decode_score(r[m]) - mx);
            g_tailw[b * TAIL + (rank - NUM_KEEP)] = e;
            local_sum += e;
        }
    }
    *(int4*)(g_sorted_idx + b * NTOK + base) =
        make_int4(idx4[0], idx4[1], idx4[2], idx4[3]);

    for (int off = 16; off > 0; off >>= 1)
        local_sum += __shfl_down_sync(0xFFFFFFFFu, local_sum, off);
    if ((tid & 31) == 0) red[tid >> 5] = local_sum;
    __syncthreads();
    if (tid < 32) {
        float v = red[tid];
        for (int off = 16; off > 0; off >>= 1)
            v += __shfl_down_sync(0xFFFFFFFFu, v, off);
        if (tid == 0) g_invsum[b] = 1.0f / v;
    }
}

// ---------------------------------------------------------------------------
// Kernel 2 (fused): tail accumulation (first TAIL_CTAS blocks) + gather copy.
// ---------------------------------------------------------------------------
__global__ __launch_bounds__(512)
void ts_main_kernel(const float* __restrict__ tokens,
                    float* __restrict__ sel,
                    float* __restrict__ extra)
{
    if (blockIdx.x < TAIL_CTAS) {
        // ---- tail path: extra_token += invsum * sum_r w_r * tokens[row_r] ----
        const int b    = blockIdx.x >> 3;
        const int g    = ((blockIdx.x & 7) << 2) | (threadIdx.x >> 7); // 0..31
        const int lane = threadIdx.x & 127;

        const int* __restrict__ sidx = g_sorted_idx + b * NTOK + NUM_KEEP;
        const float* __restrict__ w  = g_tailw + b * TAIL;
        const float4* __restrict__ tok4 = (const float4*)tokens
                                          + ((long long)b * NTOK << 7);

        float4 acc = make_float4(0.f, 0.f, 0.f, 0.f);
        int r = g;
        for (; r + NGROUP < TAIL; r += 2 * NGROUP) {
            int   i0 = sidx[r],    i1 = sidx[r + NGROUP];
            float w0 = w[r],       w1 = w[r + NGROUP];
            float4 v0 = tok4[((long long)i0 << 7) + lane];
            float4 v1 = tok4[((long long)i1 << 7) + lane];
            acc.x += w0 * v0.x + w1 * v1.x;
            acc.y += w0 * v0.y + w1 * v1.y;
            acc.z += w0 * v0.z + w1 * v1.z;
            acc.w += w0 * v0.w + w1 * v1.w;
        }
        if (r < TAIL) {
            int i0 = sidx[r];
            float w0 = w[r];
            float4 v0 = tok4[((long long)i0 << 7) + lane];
            acc.x += w0 * v0.x; acc.y += w0 * v0.y;
            acc.z += w0 * v0.z; acc.w += w0 * v0.w;
        }
        float s = g_invsum[b];
        float* dst = extra + b * CH + (lane << 2);
        atomicAdd(dst + 0, acc.x * s);
        atomicAdd(dst + 1, acc.y * s);
        atomicAdd(dst + 2, acc.z * s);
        atomicAdd(dst + 3, acc.w * s);
    } else {
        // ---- copy path: 4096 float4s per CTA, MLP=8 per thread ----
        const int cta = blockIdx.x - TAIL_CTAS;
        const int v0  = (cta << 12) + threadIdx.x;

        long long srcoff[8];
        #pragma unroll
        for (int i = 0; i < 8; ++i) {
            int v = v0 + (i << 9);
            int row  = v >> 7;                 // b*NUM_KEEP + r
            int lane = v & 127;
            int b = row / NUM_KEEP;
            int r = row - b * NUM_KEEP;
            int idx = __ldg(&g_sorted_idx[b * NTOK + r]);
            srcoff[i] = (((long long)b * NTOK + idx) << 7) + lane;
        }
        float4 val[8];
        #pragma unroll
        for (int i = 0; i < 8; ++i)
            val[i] = ((const float4*)tokens)[srcoff[i]];
        #pragma unroll
        for (int i = 0; i < 8; ++i)
            ((float4*)sel)[v0 + (i << 9)] = val[i];
    }
}

// ---------------------------------------------------------------------------
extern "C" void kernel_launch(void* const* d_in, const int* in_sizes, int n_in,
                              void* d_out, int out_size)
{
    const float* tokens = (const float*)d_in[0];
    const float* ax     = (const float*)d_in[1];
    const float* ay     = (const float*)d_in[2];

    float* out = (float*)d_out;
    float* sel   = out;                                      // B*NUM_KEEP*C
    float* extra = out + (long long)BATCH * NUM_KEEP * CH;   // B*C
    float* mask  = extra + (long long)BATCH * CH;            // B*N

    ts_sort_kernel<<<BATCH, 1024>>>(ax, ay, mask, extra);
    ts_main_kernel<<<TAIL_CTAS + COPY_CTAS, 512>>>(tokens, sel, extra);
}

// round 4
// speedup vs baseline: 2.0733x; 1.0021x over previous
#include <cuda_runtime.h>
#include <cuda_bf16.h>

#define BATCH 64
#define NTOK  4096
#define CH    512
#define NUM_KEEP 2458            // ceil(4096 * 0.6)
#define TAIL (NTOK - NUM_KEEP)   // 1638
#define C4   (CH / 4)            // 128 float4 per token row
#define NGROUP 32                // tail groups per batch
#define TAIL_CTAS (BATCH * 8)    // 512 CTAs, 4 groups of 128 lanes each
#define COPY_CTAS 4916           // TOTAL_V / 4096 float4s per CTA, exact
#define TOTAL_V (BATCH * NUM_KEEP * C4)   // 20,135,936

// scratch (device globals: no allocation allowed)
__device__ int    g_sorted_idx[BATCH * NTOK];
__device__ float  g_tailw[BATCH * TAIL];     // UN-normalized exp weights
__device__ float  g_invsum[BATCH];

// ---------------------------------------------------------------------------
// sort helpers (descending bitonic, 64-bit packed keys)
// ---------------------------------------------------------------------------
__device__ __forceinline__ float decode_score(unsigned long long kk) {
    unsigned u = (unsigned)(kk >> 32);
    return (u & 0x80000000u) ? __uint_as_float(u & 0x7FFFFFFFu)
                             : __uint_as_float(~u);
}

__device__ __forceinline__ void cmpswap(unsigned long long& a,
                                        unsigned long long& c, bool desc) {
    bool sw = desc ? (a < c) : (a > c);
    if (sw) { unsigned long long t = a; a = c; c = t; }
}

__device__ __forceinline__ void shfl_stage(unsigned long long r[4],
                                           int base, int k, int j) {
    int L = j >> 2;
    bool lower = ((base & j) == 0);
    bool desc  = ((base & k) == 0);
    bool keepmax = (lower == desc);
    #pragma unroll
    for (int m = 0; m < 4; ++m) {
        unsigned long long o = __shfl_xor_sync(0xFFFFFFFFu, r[m], L);
        r[m] = keepmax ? (r[m] > o ? r[m] : o) : (r[m] < o ? r[m] : o);
    }
}

__device__ __forceinline__ void warp_pass(unsigned long long r[4],
                                          int base, int k, int jmax) {
    for (int j = jmax; j >= 4; j >>= 1) shfl_stage(r, base, k, j);
    bool desc = ((base & k) == 0);
    cmpswap(r[0], r[2], desc);
    cmpswap(r[1], r[3], desc);
    cmpswap(r[0], r[1], desc);
    cmpswap(r[2], r[3], desc);
}

// ---------------------------------------------------------------------------
// Kernel 1: per-batch hybrid bitonic sort with PAIRED smem levels.
// Phase B processes levels (j, j/2) in one smem pass: each thread owns the
// quad {i, i+j2, i+2*j2, i+3*j2}, i = 4*t - 3*(t mod j2); all four share the
// direction bit (i & k) since j < k. 9 quad passes replace 15 level passes.
// ---------------------------------------------------------------------------
__global__ __launch_bounds__(1024)
void ts_sort_kernel(const float* __restrict__ ax,
                    const float* __restrict__ ay,
                    float* __restrict__ mask_out,
                    float* __restrict__ extra)
{
    __shared__ unsigned long long key[NTOK];   // 32 KB
    __shared__ float red[33];

    const int b    = blockIdx.x;
    const int tid  = threadIdx.x;
    const int base = ((tid >> 5) << 7) | ((tid & 31) << 2);

    // zero this batch's extra-token slice (output poisoned; tail atomics add)
    if (tid < CH) extra[b * CH + tid] = 0.0f;

    unsigned long long r[4];
    {
        float4 x = *(const float4*)(ax + b * NTOK + base);
        float4 y = *(const float4*)(ay + b * NTOK + base);
        float s[4] = { x.x + y.x, x.y + y.y, x.z + y.z, x.w + y.w };
        #pragma unroll
        for (int m = 0; m < 4; ++m) {
            unsigned u = __float_as_uint(s[m]);
            u = (u & 0x80000000u) ? ~u : (u | 0x80000000u);
            r[m] = ((unsigned long long)u << 32) | (unsigned)(~(base + m));
        }
    }

    // Phase A: k = 2..128 in registers / shuffles
    cmpswap(r[0], r[1], true);
    cmpswap(r[2], r[3], false);
    for (int k = 4; k <= 128; k <<= 1)
        warp_pass(r, base, k, (k >> 1) > 64 ? 64 : (k >> 1));

    // Phase B: k = 256..4096 : paired smem levels, then warp finish
    for (int k = 256; k <= NTOK; k <<= 1) {
        #pragma unroll
        for (int m = 0; m < 4; ++m) key[base + m] = r[m];
        __syncthreads();

        int j = k >> 1;
        while (j >= 128) {
            int j2 = j >> 1;
            int i  = (tid << 2) - 3 * (tid & (j2 - 1));
            bool d = ((i & k) == 0);
            unsigned long long a0 = key[i];
            unsigned long long a1 = key[i + j2];
            unsigned long long a2 = key[i + 2 * j2];
            unsigned long long a3 = key[i + 3 * j2];
            cmpswap(a0, a2, d);   // level j
            cmpswap(a1, a3, d);
            cmpswap(a0, a1, d);   // level j/2
            cmpswap(a2, a3, d);
            key[i]          = a0;
            key[i + j2]     = a1;
            key[i + 2 * j2] = a2;
            key[i + 3 * j2] = a3;
            __syncthreads();
            j >>= 2;              // consumed two levels
        }
        #pragma unroll
        for (int m = 0; m < 4; ++m) r[m] = key[base + m];
        warp_pass(r, base, k, j);     // j is 64 or 32 here
    }

    // softmax max = score at rank NUM_KEEP
    if (base <= NUM_KEEP && NUM_KEEP < base + 4)
        red[32] = decode_score(r[NUM_KEEP - base]);
    __syncthreads();
    const float mx = red[32];

    float local_sum = 0.f;
    int idx4[4];
    #pragma unroll
    for (int m = 0; m < 4; ++m) {
        int rank = base + m;
        int idx = (int)(~(unsigned)r[m]);
        idx4[m] = idx;
        mask_out[b * NTOK + idx] = (rank < NUM_KEEP) ? 1.0f : 0.0f;
        if (rank >= NUM_KEEP) {
            float e = expf(decode_score(r[m]) - mx);
            g_tailw[b * TAIL + (rank - NUM_KEEP)] = e;
            local_sum += e;
        }
    }
    *(int4*)(g_sorted_idx + b * NTOK + base) =
        make_int4(idx4[0], idx4[1], idx4[2], idx4[3]);

    for (int off = 16; off > 0; off >>= 1)
        local_sum += __shfl_down_sync(0xFFFFFFFFu, local_sum, off);
    if ((tid & 31) == 0) red[tid >> 5] = local_sum;
    __syncthreads();
    if (tid < 32) {
        float v = red[tid];
        for (int off = 16; off > 0; off >>= 1)
            v += __shfl_down_sync(0xFFFFFFFFu, v, off);
        if (tid == 0) g_invsum[b] = 1.0f / v;
    }
}

// ---------------------------------------------------------------------------
// Kernel 2 (fused): tail accumulation (first TAIL_CTAS blocks) + gather copy.
// (unchanged from R3 — it is at the HBM roofline)
// ---------------------------------------------------------------------------
__global__ __launch_bounds__(512)
void ts_main_kernel(const float* __restrict__ tokens,
                    float* __restrict__ sel,
                    float* __restrict__ extra)
{
    if (blockIdx.x < TAIL_CTAS) {
        const int b    = blockIdx.x >> 3;
        const int g    = ((blockIdx.x & 7) << 2) | (threadIdx.x >> 7); // 0..31
        const int lane = threadIdx.x & 127;

        const int* __restrict__ sidx = g_sorted_idx + b * NTOK + NUM_KEEP;
        const float* __restrict__ w  = g_tailw + b * TAIL;
        const float4* __restrict__ tok4 = (const float4*)tokens
                                          + ((long long)b * NTOK << 7);

        float4 acc = make_float4(0.f, 0.f, 0.f, 0.f);
        int r = g;
        for (; r + NGROUP < TAIL; r += 2 * NGROUP) {
            int   i0 = sidx[r],    i1 = sidx[r + NGROUP];
            float w0 = w[r],       w1 = w[r + NGROUP];
            float4 v0 = tok4[((long long)i0 << 7) + lane];
            float4 v1 = tok4[((long long)i1 << 7) + lane];
            acc.x += w0 * v0.x + w1 * v1.x;
            acc.y += w0 * v0.y + w1 * v1.y;
            acc.z += w0 * v0.z + w1 * v1.z;
            acc.w += w0 * v0.w + w1 * v1.w;
        }
        if (r < TAIL) {
            int i0 = sidx[r];
            float w0 = w[r];
            float4 v0 = tok4[((long long)i0 << 7) + lane];
            acc.x += w0 * v0.x; acc.y += w0 * v0.y;
            acc.z += w0 * v0.z; acc.w += w0 * v0.w;
        }
        float s = g_invsum[b];
        float* dst = extra + b * CH + (lane << 2);
        atomicAdd(dst + 0, acc.x * s);
        atomicAdd(dst + 1, acc.y * s);
        atomicAdd(dst + 2, acc.z * s);
        atomicAdd(dst + 3, acc.w * s);
    } else {
        const int cta = blockIdx.x - TAIL_CTAS;
        const int v0  = (cta << 12) + threadIdx.x;

        long long srcoff[8];
        #pragma unroll
        for (int i = 0; i < 8; ++i) {
            int v = v0 + (i << 9);
            int row  = v >> 7;                 // b*NUM_KEEP + r
            int lane = v & 127;
            int b = row / NUM_KEEP;
            int r = row - b * NUM_KEEP;
            int idx = __ldg(&g_sorted_idx[b * NTOK + r]);
            srcoff[i] = (((long long)b * NTOK + idx) << 7) + lane;
        }
        float4 val[8];
        #pragma unroll
        for (int i = 0; i < 8; ++i)
            val[i] = ((const float4*)tokens)[srcoff[i]];
        #pragma unroll
        for (int i = 0; i < 8; ++i)
            ((float4*)sel)[v0 + (i << 9)] = val[i];
    }
}

// ---------------------------------------------------------------------------
extern "C" void kernel_launch(void* const* d_in, const int* in_sizes, int n_in,
                              void* d_out, int out_size)
{
    const float* tokens = (const float*)d_in[0];
    const float* ax     = (const float*)d_in[1];
    const float* ay     = (const float*)d_in[2];

    float* out = (float*)d_out;
    float* sel   = out;                                      // B*NUM_KEEP*C
    float* extra = out + (long long)BATCH * NUM_KEEP * CH;   // B*C
    float* mask  = extra + (long long)BATCH * CH;            // B*N

    ts_sort_kernel<<<BATCH, 1024>>>(ax, ay, mask, extra);
    ts_main_kernel<<<TAIL_CTAS + COPY_CTAS, 512>>>(tokens, sel, extra);
}

// round 5
// speedup vs baseline: 2.2326x; 1.0769x over previous
#include <cuda_runtime.h>
#include <cuda_bf16.h>

#define BATCH 64
#define NTOK  4096
#define CH    512
#define NUM_KEEP 2458            // ceil(4096 * 0.6)
#define TAIL (NTOK - NUM_KEEP)   // 1638
#define C4   (CH / 4)            // 128 float4 per token row
#define NGROUP 32                // tail groups per batch
#define TAIL_CTAS (BATCH * 8)    // 512 CTAs, 4 groups of 128 lanes each
#define COPY_CTAS 4916           // TOTAL_V / 4096 float4s per CTA, exact
#define CHUNK 1024               // elements per S1 CTA

// scratch (device globals: no allocation allowed)
__device__ unsigned long long g_keys[BATCH * NTOK];   // 2 MB
__device__ int    g_sorted_idx[BATCH * NTOK];
__device__ float  g_tailw[BATCH * TAIL];     // UN-normalized exp weights
__device__ float  g_invsum[BATCH];

// ---------------------------------------------------------------------------
// sort helpers (bitonic, 64-bit packed keys; flip inverts every comparator)
// ---------------------------------------------------------------------------
__device__ __forceinline__ float decode_score(unsigned long long kk) {
    unsigned u = (unsigned)(kk >> 32);
    return (u & 0x80000000u) ? __uint_as_float(u & 0x7FFFFFFFu)
                             : __uint_as_float(~u);
}

__device__ __forceinline__ void cmpswap(unsigned long long& a,
                                        unsigned long long& c, bool desc) {
    bool sw = desc ? (a < c) : (a > c);
    if (sw) { unsigned long long t = a; a = c; c = t; }
}

__device__ __forceinline__ void shfl_stage(unsigned long long r[4],
                                           int base, int k, int j, bool flip) {
    int L = j >> 2;
    bool lower = ((base & j) == 0);
    bool desc  = (((base & k) == 0) != flip);
    bool keepmax = (lower == desc);
    #pragma unroll
    for (int m = 0; m < 4; ++m) {
        unsigned long long o = __shfl_xor_sync(0xFFFFFFFFu, r[m], L);
        r[m] = keepmax ? (r[m] > o ? r[m] : o) : (r[m] < o ? r[m] : o);
    }
}

__device__ __forceinline__ void warp_pass(unsigned long long r[4],
                                          int base, int k, int jmax, bool flip) {
    for (int j = jmax; j >= 4; j >>= 1) shfl_stage(r, base, k, j, flip);
    bool desc = (((base & k) == 0) != flip);
    cmpswap(r[0], r[2], desc);
    cmpswap(r[1], r[3], desc);
    cmpswap(r[0], r[1], desc);
    cmpswap(r[2], r[3], desc);
}

// ---------------------------------------------------------------------------
// Kernel S1: 4 CTAs per batch, each sorts a 1024-element chunk.
// Odd chunks sort ascending (flip) so the result is bitonic-network-
// equivalent to having completed all stages k<=1024 of the 4096 sort.
// ---------------------------------------------------------------------------
__global__ __launch_bounds__(256)
void ts_sort1_kernel(const float* __restrict__ ax,
                     const float* __restrict__ ay)
{
    __shared__ unsigned long long key[CHUNK];   // 8 KB

    const int chunk = blockIdx.x;        // 0..255
    const int b     = chunk >> 2;
    const int c     = chunk & 3;
    const bool flip = (c & 1);
    const int tid   = threadIdx.x;
    const int base  = ((tid >> 5) << 7) | ((tid & 31) << 2);   // 0..1023
    const int gbase = (c << 10) + base;  // token index within batch

    unsigned long long r[4];
    {
        float4 x = *(const float4*)(ax + b * NTOK + gbase);
        float4 y = *(const float4*)(ay + b * NTOK + gbase);
        float s[4] = { x.x + y.x, x.y + y.y, x.z + y.z, x.w + y.w };
        #pragma unroll
        for (int m = 0; m < 4; ++m) {
            unsigned u = __float_as_uint(s[m]);
            u = (u & 0x80000000u) ? ~u : (u | 0x80000000u);
            r[m] = ((unsigned long long)u << 32) | (unsigned)(~(gbase + m));
        }
    }

    // Phase A: k = 2..128 in registers / shuffles
    cmpswap(r[0], r[1], !flip);
    cmpswap(r[2], r[3], flip);
    for (int k = 4; k <= 128; k <<= 1)
        warp_pass(r, base, k, (k >> 1) > 64 ? 64 : (k >> 1), flip);

    // Phase B: k = 256, 512, 1024 : paired smem levels + warp finish
    for (int k = 256; k <= CHUNK; k <<= 1) {
        #pragma unroll
        for (int m = 0; m < 4; ++m) key[base + m] = r[m];
        __syncthreads();
        int j = k >> 1;
        while (j >= 128) {
            int j2 = j >> 1;
            int i  = (tid << 2) - 3 * (tid & (j2 - 1));
            bool d = (((i & k) == 0) != flip);
            unsigned long long a0 = key[i];
            unsigned long long a1 = key[i + j2];
            unsigned long long a2 = key[i + 2 * j2];
            unsigned long long a3 = key[i + 3 * j2];
            cmpswap(a0, a2, d);
            cmpswap(a1, a3, d);
            cmpswap(a0, a1, d);
            cmpswap(a2, a3, d);
            key[i]          = a0;
            key[i + j2]     = a1;
            key[i + 2 * j2] = a2;
            key[i + 3 * j2] = a3;
            __syncthreads();
            j >>= 2;
        }
        #pragma unroll
        for (int m = 0; m < 4; ++m) r[m] = key[base + m];
        warp_pass(r, base, k, j, flip);
    }

    // store sorted chunk (vectorized u64x2)
    unsigned long long* dst = g_keys + b * NTOK + gbase;
    ((ulonglong2*)dst)[0] = make_ulonglong2(r[0], r[1]);
    ((ulonglong2*)dst)[1] = make_ulonglong2(r[2], r[3]);
}

// ---------------------------------------------------------------------------
// Kernel S2: one CTA per batch finishes stages k = 2048, 4096, then the
// epilogue (mask, sorted idx, tail exp weights, invsum, zero extra).
// ---------------------------------------------------------------------------
__global__ __launch_bounds__(1024)
void ts_sort2_kernel(float* __restrict__ mask_out,
                     float* __restrict__ extra)
{
    __shared__ unsigned long long key[NTOK];   // 32 KB
    __shared__ float red[33];

    const int b    = blockIdx.x;
    const int tid  = threadIdx.x;
    const int base = ((tid >> 5) << 7) | ((tid & 31) << 2);   // 0..4095

    if (tid < CH) extra[b * CH + tid] = 0.0f;

    unsigned long long r[4];
    {
        const unsigned long long* src = g_keys + b * NTOK + base;
        ulonglong2 p0 = ((const ulonglong2*)src)[0];
        ulonglong2 p1 = ((const ulonglong2*)src)[1];
        r[0] = p0.x; r[1] = p0.y; r[2] = p1.x; r[3] = p1.y;
    }

    // stages k = 2048, 4096 : paired smem levels + warp finish
    for (int k = 2048; k <= NTOK; k <<= 1) {
        #pragma unroll
        for (int m = 0; m < 4; ++m) key[base + m] = r[m];
        __syncthreads();
        int j = k >> 1;
        while (j >= 128) {
            int j2 = j >> 1;
            int i  = (tid << 2) - 3 * (tid & (j2 - 1));
            bool d = ((i & k) == 0);
            unsigned long long a0 = key[i];
            unsigned long long a1 = key[i + j2];
            unsigned long long a2 = key[i + 2 * j2];
            unsigned long long a3 = key[i + 3 * j2];
            cmpswap(a0, a2, d);
            cmpswap(a1, a3, d);
            cmpswap(a0, a1, d);
            cmpswap(a2, a3, d);
            key[i]          = a0;
            key[i + j2]     = a1;
            key[i + 2 * j2] = a2;
            key[i + 3 * j2] = a3;
            __syncthreads();
            j >>= 2;
        }
        #pragma unroll
        for (int m = 0; m < 4; ++m) r[m] = key[base + m];
        warp_pass(r, base, k, j, false);
    }

    // softmax max = score at rank NUM_KEEP
    if (base <= NUM_KEEP && NUM_KEEP < base + 4)
        red[32] = decode_score(r[NUM_KEEP - base]);
    __syncthreads();
    const float mx = red[32];

    float local_sum = 0.f;
    int idx4[4];
    #pragma unroll
    for (int m = 0; m < 4; ++m) {
        int rank = base + m;
        int idx = (int)(~(unsigned)r[m]);
        idx4[m] = idx;
        mask_out[b * NTOK + idx] = (rank < NUM_KEEP) ? 1.0f : 0.0f;
        if (rank >= NUM_KEEP) {
            float e = expf(decode_score(r[m]) - mx);
            g_tailw[b * TAIL + (rank - NUM_KEEP)] = e;
            local_sum += e;
        }
    }
    *(int4*)(g_sorted_idx + b * NTOK + base) =
        make_int4(idx4[0], idx4[1], idx4[2], idx4[3]);

    for (int off = 16; off > 0; off >>= 1)
        local_sum += __shfl_down_sync(0xFFFFFFFFu, local_sum, off);
    if ((tid & 31) == 0) red[tid >> 5] = local_sum;
    __syncthreads();
    if (tid < 32) {
        float v = red[tid];
        for (int off = 16; off > 0; off >>= 1)
            v += __shfl_down_sync(0xFFFFFFFFu, v, off);
        if (tid == 0) g_invsum[b] = 1.0f / v;
    }
}

// ---------------------------------------------------------------------------
// Kernel 2 (fused): tail accumulation + gather copy, streaming cache hints.
// ---------------------------------------------------------------------------
__global__ __launch_bounds__(512)
void ts_main_kernel(const float* __restrict__ tokens,
                    float* __restrict__ sel,
                    float* __restrict__ extra)
{
    if (blockIdx.x < TAIL_CTAS) {
        const int b    = blockIdx.x >> 3;
        const int g    = ((blockIdx.x & 7) << 2) | (threadIdx.x >> 7); // 0..31
        const int lane = threadIdx.x & 127;

        const int* __restrict__ sidx = g_sorted_idx + b * NTOK + NUM_KEEP;
        const float* __restrict__ w  = g_tailw + b * TAIL;
        const float4* __restrict__ tok4 = (const float4*)tokens
                                          + ((long long)b * NTOK << 7);

        float4 acc = make_float4(0.f, 0.f, 0.f, 0.f);
        int r = g;
        for (; r + NGROUP < TAIL; r += 2 * NGROUP) {
            int   i0 = sidx[r],    i1 = sidx[r + NGROUP];
            float w0 = w[r],       w1 = w[r + NGROUP];
            float4 v0 = __ldcs(&tok4[((long long)i0 << 7) + lane]);
            float4 v1 = __ldcs(&tok4[((long long)i1 << 7) + lane]);
            acc.x += w0 * v0.x + w1 * v1.x;
            acc.y += w0 * v0.y + w1 * v1.y;
            acc.z += w0 * v0.z + w1 * v1.z;
            acc.w += w0 * v0.w + w1 * v1.w;
        }
        if (r < TAIL) {
            int i0 = sidx[r];
            float w0 = w[r];
            float4 v0 = __ldcs(&tok4[((long long)i0 << 7) + lane]);
            acc.x += w0 * v0.x; acc.y += w0 * v0.y;
            acc.z += w0 * v0.z; acc.w += w0 * v0.w;
        }
        float s = g_invsum[b];
        float* dst = extra + b * CH + (lane << 2);
        atomicAdd(dst + 0, acc.x * s);
        atomicAdd(dst + 1, acc.y * s);
        atomicAdd(dst + 2, acc.z * s);
        atomicAdd(dst + 3, acc.w * s);
    } else {
        const int cta = blockIdx.x - TAIL_CTAS;
        const int v0  = (cta << 12) + threadIdx.x;

        long long srcoff[8];
        #pragma unroll
        for (int i = 0; i < 8; ++i) {
            int v = v0 + (i << 9);
            int row  = v >> 7;                 // b*NUM_KEEP + r
            int lane = v & 127;
            int b = row / NUM_KEEP;
            int r = row - b * NUM_KEEP;
            int idx = __ldg(&g_sorted_idx[b * NTOK + r]);
            srcoff[i] = (((long long)b * NTOK + idx) << 7) + lane;
        }
        float4 val[8];
        #pragma unroll
        for (int i = 0; i < 8; ++i)
            val[i] = __ldcs(((const float4*)tokens) + srcoff[i]);
        #pragma unroll
        for (int i = 0; i < 8; ++i)
            __stcs(((float4*)sel) + v0 + (i << 9), val[i]);
    }
}

// ---------------------------------------------------------------------------
extern "C" void kernel_launch(void* const* d_in, const int* in_sizes, int n_in,
                              void* d_out, int out_size)
{
    const float* tokens = (const float*)d_in[0];
    const float* ax     = (const float*)d_in[1];
    const float* ay     = (const float*)d_in[2];

    float* out = (float*)d_out;
    float* sel   = out;                                      // B*NUM_KEEP*C
    float* extra = out + (long long)BATCH * NUM_KEEP * CH;   // B*C
    float* mask  = extra + (long long)BATCH * CH;            // B*N

    ts_sort1_kernel<<<BATCH * 4, 256>>>(ax, ay);
    ts_sort2_kernel<<<BATCH, 1024>>>(mask, extra);
    ts_main_kernel<<<TAIL_CTAS + COPY_CTAS, 512>>>(tokens, sel, extra);
}